// round 15
// baseline (speedup 1.0000x reference)
#include <cuda_runtime.h>
#include <cuda_fp16.h>
#include <cuda_bf16.h>

// Problem shapes (fixed by the dataset):
//   text:        [16, 2048, 256] f32      d_in[0]
//   const_mat:   [16, 2048, 2048] i32     d_in[1]   (UNUSED: softmax rows sum to 1)
//   const_labels:[16, 2048, 8] i32        d_in[2]
//   emb_table:   [100, 128] f32           d_in[3]
//   attn_W:      [256, 384] f32           d_in[4]   (UNUSED: cancels in softmax)
//   attn_b:      [256] f32                d_in[5]   (UNUSED)
//   fc_W:        [256, 128] f32           d_in[6]
//   fc_b:        [256] f32                d_in[7]
//   out:         [16, 2048, 256] f32
//
// Collapse: out[pos,d] = relu( text[pos,d] + sum_{k=0..7} G[labels[pos,k], d] )
// with G[n,d] = 0.125 * (fc_b[d] + emb_table[n] . fc_W[d]), G stored fp16.
//
// R15 = R14 + PDL retry. R8's PDL failed because build_G was 4-5us (uncoalesced
// fc_W) -- longer than the overlap window. R14 fixed build_G to ~0.7us, which
// now fits under the fused kernel's G-independent text/label prologue.
// Fused body unchanged from R12/R14 (13.92us, converged).

#define CN    100
#define CD    128
#define DIM   256
#define KLBL  8

__device__ __half g_Gh[CN * DIM];  // 50 KB fp16 table

// ---------------------------------------------------------------------------
// Kernel A: G[n,d] = 0.125 * (fc_b[d] + sum_c emb_table[n,c] * fc_W[d,c])
// grid = (CN, 4), block = 256. Warp computes one (n,d) per iteration, lanes
// spanning c. All fc_W traffic coalesced. Triggers PDL completion at end.
// ---------------------------------------------------------------------------
__global__ void __launch_bounds__(256) build_G_kernel(
    const float* __restrict__ emb_table,
    const float* __restrict__ fc_W,
    const float* __restrict__ fc_b)
{
    const int n   = blockIdx.x;
    const int tid = threadIdx.x;

    __shared__ float4 se4[CD / 4];   // emb row n as float4
    if (tid < CD / 4)
        se4[tid] = reinterpret_cast<const float4*>(emb_table + n * CD)[tid];
    __syncthreads();

    const int warp = tid >> 5;
    const int lane = tid & 31;
    const float4 e = se4[lane];      // lane's c-chunk (conflict-free LDS)

    const float4* W4 = reinterpret_cast<const float4*>(fc_W);

    #pragma unroll
    for (int i = 0; i < 8; i++) {
        const int d = (blockIdx.y << 6) + (i << 3) + warp;   // 0..255

        // Coalesced: lane reads fc_W[d, 4*lane .. 4*lane+3].
        const float4 w = __ldg(W4 + d * 32 + lane);
        float p = w.x * e.x + w.y * e.y + w.z * e.z + w.w * e.w;

        p += __shfl_xor_sync(0xFFFFFFFFu, p, 16);
        p += __shfl_xor_sync(0xFFFFFFFFu, p, 8);
        p += __shfl_xor_sync(0xFFFFFFFFu, p, 4);
        p += __shfl_xor_sync(0xFFFFFFFFu, p, 2);
        p += __shfl_xor_sync(0xFFFFFFFFu, p, 1);

        if (lane == 0)
            g_Gh[n * DIM + d] = __float2half_rn(0.125f * (p + __ldg(fc_b + d)));
    }

    // Signal the dependent grid that our global writes will be visible
    // after its cudaGridDependencySynchronize().
    cudaTriggerProgrammaticLaunchCompletion();
}

// ---------------------------------------------------------------------------
// Kernel B: fused gather-add-relu (body identical to R12/R14 best) with a
// grid-dependency sync between the G-independent prologue and the gathers.
// ---------------------------------------------------------------------------
__device__ __forceinline__ __half2 as_h2(unsigned u) {
    return *reinterpret_cast<const __half2*>(&u);
}

// ld.global.lu float4: last-use in L1 (evict-first locally), default L2.
__device__ __forceinline__ float4 ldlu_f4(const float4* p) {
    float4 v;
    asm volatile("ld.global.lu.v4.f32 {%0,%1,%2,%3}, [%4];"
                 : "=f"(v.x), "=f"(v.y), "=f"(v.z), "=f"(v.w)
                 : "l"(p));
    return v;
}

__device__ __forceinline__ float4 reduce8(
    const uint2& u0, const uint2& u1, const uint2& u2, const uint2& u3,
    const uint2& u4, const uint2& u5, const uint2& u6, const uint2& u7,
    const float4& t)
{
    const __half2 p0lo = __hadd2(as_h2(u0.x), as_h2(u1.x));
    const __half2 p0hi = __hadd2(as_h2(u0.y), as_h2(u1.y));
    const __half2 p1lo = __hadd2(as_h2(u2.x), as_h2(u3.x));
    const __half2 p1hi = __hadd2(as_h2(u2.y), as_h2(u3.y));
    const __half2 p2lo = __hadd2(as_h2(u4.x), as_h2(u5.x));
    const __half2 p2hi = __hadd2(as_h2(u4.y), as_h2(u5.y));
    const __half2 p3lo = __hadd2(as_h2(u6.x), as_h2(u7.x));
    const __half2 p3hi = __hadd2(as_h2(u6.y), as_h2(u7.y));

    const float2 f0lo = __half22float2(p0lo);
    const float2 f1lo = __half22float2(p1lo);
    const float2 f2lo = __half22float2(p2lo);
    const float2 f3lo = __half22float2(p3lo);
    const float2 f0hi = __half22float2(p0hi);
    const float2 f1hi = __half22float2(p1hi);
    const float2 f2hi = __half22float2(p2hi);
    const float2 f3hi = __half22float2(p3hi);

    float4 r;
    r.x = fmaxf(t.x + (f0lo.x + f1lo.x) + (f2lo.x + f3lo.x), 0.0f);
    r.y = fmaxf(t.y + (f0lo.y + f1lo.y) + (f2lo.y + f3lo.y), 0.0f);
    r.z = fmaxf(t.z + (f0hi.x + f1hi.x) + (f2hi.x + f3hi.x), 0.0f);
    r.w = fmaxf(t.w + (f0hi.y + f1hi.y) + (f2hi.y + f3hi.y), 0.0f);
    return r;
}

__global__ void __launch_bounds__(256, 6) fused_gather_kernel(
    const float4* __restrict__ text4,
    const int*    __restrict__ labels,
    float4*       __restrict__ out4)
{
    const int gid = blockIdx.x * blockDim.x + threadIdx.x;   // exact grid

    const int pos = gid >> 5;        // warp-uniform (warp = one position)
    const int d4  = gid & 31;        // uint2 slot 0..31; twin at d4+32

    // ---- Prologue: independent of build_G (overlaps with it under PDL).
    const int4* lb = reinterpret_cast<const int4*>(labels) + (pos << 1);
    const int4 l0 = __ldg(lb + 0);
    const int4 l1 = __ldg(lb + 1);

    const int idxA = (pos << 6) + d4;        // output float4 index, low half
    const int idxB = idxA + 32;              // high half

    const float4 tA = ldlu_f4(text4 + idxA);
    const float4 tB = ldlu_f4(text4 + idxB);

    // ---- Wait for build_G's g_Gh writes.
    cudaGridDependencySynchronize();

    const uint2* __restrict__ Gh = reinterpret_cast<const uint2*>(g_Gh);

    const int b0 = (l0.x << 6) + d4;
    const int b1 = (l0.y << 6) + d4;
    const int b2 = (l0.z << 6) + d4;
    const int b3 = (l0.w << 6) + d4;
    const int b4 = (l1.x << 6) + d4;
    const int b5 = (l1.y << 6) + d4;
    const int b6 = (l1.z << 6) + d4;
    const int b7 = (l1.w << 6) + d4;

    const uint2 a0 = __ldg(Gh + b0);
    const uint2 a1 = __ldg(Gh + b1);
    const uint2 a2 = __ldg(Gh + b2);
    const uint2 a3 = __ldg(Gh + b3);
    const uint2 a4 = __ldg(Gh + b4);
    const uint2 a5 = __ldg(Gh + b5);
    const uint2 a6 = __ldg(Gh + b6);
    const uint2 a7 = __ldg(Gh + b7);

    const uint2 c0 = __ldg(Gh + b0 + 32);
    const uint2 c1 = __ldg(Gh + b1 + 32);
    const uint2 c2 = __ldg(Gh + b2 + 32);
    const uint2 c3 = __ldg(Gh + b3 + 32);
    const uint2 c4 = __ldg(Gh + b4 + 32);
    const uint2 c5 = __ldg(Gh + b5 + 32);
    const uint2 c6 = __ldg(Gh + b6 + 32);
    const uint2 c7 = __ldg(Gh + b7 + 32);

    const float4 rA = reduce8(a0, a1, a2, a3, a4, a5, a6, a7, tA);
    const float4 rB = reduce8(c0, c1, c2, c3, c4, c5, c6, c7, tB);

    __stcs(out4 + idxA, rA);
    __stcs(out4 + idxB, rB);
}

// ---------------------------------------------------------------------------
extern "C" void kernel_launch(void* const* d_in, const int* in_sizes, int n_in,
                              void* d_out, int out_size)
{
    const float* text      = (const float*)d_in[0];
    const int*   labels    = (const int*)  d_in[2];
    const float* emb_table = (const float*)d_in[3];
    const float* fc_W      = (const float*)d_in[6];
    const float* fc_b      = (const float*)d_in[7];
    float*       out       = (float*)d_out;

    const int ntotal = in_sizes[0];        // 8,388,608
    const int nhalf  = ntotal / 8;         // 1,048,576 threads (2 float4 each)

    build_G_kernel<<<dim3(CN, 4), 256>>>(emb_table, fc_W, fc_b);

    const int block = 256;
    const int grid  = nhalf / block;       // 4096 exactly

    cudaLaunchConfig_t cfg = {};
    cfg.gridDim  = dim3(grid, 1, 1);
    cfg.blockDim = dim3(block, 1, 1);
    cfg.dynamicSmemBytes = 0;
    cfg.stream = 0;

    cudaLaunchAttribute attrs[1];
    attrs[0].id = cudaLaunchAttributeProgrammaticStreamSerialization;
    attrs[0].val.programmaticStreamSerializationAllowed = 1;
    cfg.attrs = attrs;
    cfg.numAttrs = 1;

    cudaLaunchKernelEx(&cfg, fused_gather_kernel,
                       reinterpret_cast<const float4*>(text),
                       labels,
                       reinterpret_cast<float4*>(out));
}

// round 16
// speedup vs baseline: 1.0171x; 1.0171x over previous
#include <cuda_runtime.h>
#include <cuda_fp16.h>
#include <cuda_bf16.h>

// Problem shapes (fixed by the dataset):
//   text:        [16, 2048, 256] f32      d_in[0]
//   const_mat:   [16, 2048, 2048] i32     d_in[1]   (UNUSED: softmax rows sum to 1)
//   const_labels:[16, 2048, 8] i32        d_in[2]
//   emb_table:   [100, 128] f32           d_in[3]
//   attn_W:      [256, 384] f32           d_in[4]   (UNUSED: cancels in softmax)
//   attn_b:      [256] f32                d_in[5]   (UNUSED)
//   fc_W:        [256, 128] f32           d_in[6]
//   fc_b:        [256] f32                d_in[7]
//   out:         [16, 2048, 256] f32
//
// Collapse: out[pos,d] = relu( text[pos,d] + sum_{k=0..7} G[labels[pos,k], d] )
// with G[n,d] = 0.125 * (fc_b[d] + emb_table[n] . fc_W[d]), G stored fp16.
//
// R16 = R14 (best, 17.12us) + (a) zero smem carveout on the fused kernel so
// L1D gets the full 228 KB (G + more text lines resident), (b) load order
// A-gathers -> text -> C-gathers with the A-reduction starting while C loads
// are in flight (shorter scoreboard tail per one-shot warp). PDL dropped:
// R15 showed the grid-dependency sync costs what the overlap saves.

#define CN    100
#define CD    128
#define DIM   256
#define KLBL  8

__device__ __half g_Gh[CN * DIM];  // 50 KB fp16 table

// ---------------------------------------------------------------------------
// Kernel A: G[n,d] = 0.125 * (fc_b[d] + sum_c emb_table[n,c] * fc_W[d,c])
// grid = (CN, 4), block = 256. Warp computes one (n,d) per iteration, lanes
// spanning c. All fc_W traffic coalesced.
// ---------------------------------------------------------------------------
__global__ void __launch_bounds__(256) build_G_kernel(
    const float* __restrict__ emb_table,
    const float* __restrict__ fc_W,
    const float* __restrict__ fc_b)
{
    const int n   = blockIdx.x;
    const int tid = threadIdx.x;

    __shared__ float4 se4[CD / 4];   // emb row n as float4
    if (tid < CD / 4)
        se4[tid] = reinterpret_cast<const float4*>(emb_table + n * CD)[tid];
    __syncthreads();

    const int warp = tid >> 5;
    const int lane = tid & 31;
    const float4 e = se4[lane];      // lane's c-chunk (conflict-free LDS)

    const float4* W4 = reinterpret_cast<const float4*>(fc_W);

    #pragma unroll
    for (int i = 0; i < 8; i++) {
        const int d = (blockIdx.y << 6) + (i << 3) + warp;   // 0..255

        // Coalesced: lane reads fc_W[d, 4*lane .. 4*lane+3].
        const float4 w = __ldg(W4 + d * 32 + lane);
        float p = w.x * e.x + w.y * e.y + w.z * e.z + w.w * e.w;

        p += __shfl_xor_sync(0xFFFFFFFFu, p, 16);
        p += __shfl_xor_sync(0xFFFFFFFFu, p, 8);
        p += __shfl_xor_sync(0xFFFFFFFFu, p, 4);
        p += __shfl_xor_sync(0xFFFFFFFFu, p, 2);
        p += __shfl_xor_sync(0xFFFFFFFFu, p, 1);

        if (lane == 0)
            g_Gh[n * DIM + d] = __float2half_rn(0.125f * (p + __ldg(fc_b + d)));
    }
}

// ---------------------------------------------------------------------------
// Kernel B: fused gather-add-relu. gid -> pos = gid>>5, d4 = gid&31.
// Thread covers output float4s (pos, d4) and (pos, d4+32).
// ---------------------------------------------------------------------------
__device__ __forceinline__ __half2 as_h2(unsigned u) {
    return *reinterpret_cast<const __half2*>(&u);
}

// ld.global.lu float4: last-use in L1 (evict-first locally), default L2.
__device__ __forceinline__ float4 ldlu_f4(const float4* p) {
    float4 v;
    asm volatile("ld.global.lu.v4.f32 {%0,%1,%2,%3}, [%4];"
                 : "=f"(v.x), "=f"(v.y), "=f"(v.z), "=f"(v.w)
                 : "l"(p));
    return v;
}

__device__ __forceinline__ float4 reduce8(
    const uint2& u0, const uint2& u1, const uint2& u2, const uint2& u3,
    const uint2& u4, const uint2& u5, const uint2& u6, const uint2& u7,
    const float4& t)
{
    const __half2 p0lo = __hadd2(as_h2(u0.x), as_h2(u1.x));
    const __half2 p0hi = __hadd2(as_h2(u0.y), as_h2(u1.y));
    const __half2 p1lo = __hadd2(as_h2(u2.x), as_h2(u3.x));
    const __half2 p1hi = __hadd2(as_h2(u2.y), as_h2(u3.y));
    const __half2 p2lo = __hadd2(as_h2(u4.x), as_h2(u5.x));
    const __half2 p2hi = __hadd2(as_h2(u4.y), as_h2(u5.y));
    const __half2 p3lo = __hadd2(as_h2(u6.x), as_h2(u7.x));
    const __half2 p3hi = __hadd2(as_h2(u6.y), as_h2(u7.y));

    const float2 f0lo = __half22float2(p0lo);
    const float2 f1lo = __half22float2(p1lo);
    const float2 f2lo = __half22float2(p2lo);
    const float2 f3lo = __half22float2(p3lo);
    const float2 f0hi = __half22float2(p0hi);
    const float2 f1hi = __half22float2(p1hi);
    const float2 f2hi = __half22float2(p2hi);
    const float2 f3hi = __half22float2(p3hi);

    float4 r;
    r.x = fmaxf(t.x + (f0lo.x + f1lo.x) + (f2lo.x + f3lo.x), 0.0f);
    r.y = fmaxf(t.y + (f0lo.y + f1lo.y) + (f2lo.y + f3lo.y), 0.0f);
    r.z = fmaxf(t.z + (f0hi.x + f1hi.x) + (f2hi.x + f3hi.x), 0.0f);
    r.w = fmaxf(t.w + (f0hi.y + f1hi.y) + (f2hi.y + f3hi.y), 0.0f);
    return r;
}

__global__ void __launch_bounds__(256, 6) fused_gather_kernel(
    const float4* __restrict__ text4,
    const int*    __restrict__ labels,
    float4*       __restrict__ out4)
{
    const int gid = blockIdx.x * blockDim.x + threadIdx.x;   // exact grid

    const int pos = gid >> 5;        // warp-uniform (warp = one position)
    const int d4  = gid & 31;        // uint2 slot 0..31; twin at d4+32

    const int4* lb = reinterpret_cast<const int4*>(labels) + (pos << 1);
    const int4 l0 = __ldg(lb + 0);
    const int4 l1 = __ldg(lb + 1);

    const uint2* __restrict__ Gh = reinterpret_cast<const uint2*>(g_Gh);

    const int idxA = (pos << 6) + d4;        // output float4 index, low half
    const int idxB = idxA + 32;              // high half

    const int b0 = (l0.x << 6) + d4;
    const int b1 = (l0.y << 6) + d4;
    const int b2 = (l0.z << 6) + d4;
    const int b3 = (l0.w << 6) + d4;
    const int b4 = (l1.x << 6) + d4;
    const int b5 = (l1.y << 6) + d4;
    const int b6 = (l1.z << 6) + d4;
    const int b7 = (l1.w << 6) + d4;

    // ---- A-half gathers first...
    const uint2 a0 = __ldg(Gh + b0);
    const uint2 a1 = __ldg(Gh + b1);
    const uint2 a2 = __ldg(Gh + b2);
    const uint2 a3 = __ldg(Gh + b3);
    const uint2 a4 = __ldg(Gh + b4);
    const uint2 a5 = __ldg(Gh + b5);
    const uint2 a6 = __ldg(Gh + b6);
    const uint2 a7 = __ldg(Gh + b7);

    // ...then text (longest latency)...
    const float4 tA = ldlu_f4(text4 + idxA);
    const float4 tB = ldlu_f4(text4 + idxB);

    // ...then C-half gathers. The A reduction below only waits on a0..a7+tA,
    // so it starts while c0..c7 are still in flight (shorter warp tail).
    const uint2 c0 = __ldg(Gh + b0 + 32);
    const uint2 c1 = __ldg(Gh + b1 + 32);
    const uint2 c2 = __ldg(Gh + b2 + 32);
    const uint2 c3 = __ldg(Gh + b3 + 32);
    const uint2 c4 = __ldg(Gh + b4 + 32);
    const uint2 c5 = __ldg(Gh + b5 + 32);
    const uint2 c6 = __ldg(Gh + b6 + 32);
    const uint2 c7 = __ldg(Gh + b7 + 32);

    const float4 rA = reduce8(a0, a1, a2, a3, a4, a5, a6, a7, tA);
    __stcs(out4 + idxA, rA);

    const float4 rB = reduce8(c0, c1, c2, c3, c4, c5, c6, c7, tB);
    __stcs(out4 + idxB, rB);
}

// ---------------------------------------------------------------------------
extern "C" void kernel_launch(void* const* d_in, const int* in_sizes, int n_in,
                              void* d_out, int out_size)
{
    const float* text      = (const float*)d_in[0];
    const int*   labels    = (const int*)  d_in[2];
    const float* emb_table = (const float*)d_in[3];
    const float* fc_W      = (const float*)d_in[6];
    const float* fc_b      = (const float*)d_in[7];
    float*       out       = (float*)d_out;

    const int ntotal = in_sizes[0];        // 8,388,608
    const int nhalf  = ntotal / 8;         // 1,048,576 threads (2 float4 each)

    // Max L1D: no smem used by the fused kernel, so request 0% carveout.
    // (Attribute set is idempotent and graph-capture safe.)
    cudaFuncSetAttribute(fused_gather_kernel,
                         cudaFuncAttributePreferredSharedMemoryCarveout, 0);

    build_G_kernel<<<dim3(CN, 4), 256>>>(emb_table, fc_W, fc_b);

    const int block = 256;
    const int grid  = nhalf / block;       // 4096 exactly
    fused_gather_kernel<<<grid, block>>>(
        reinterpret_cast<const float4*>(text),
        labels,
        reinterpret_cast<float4*>(out));
}